// round 10
// baseline (speedup 1.0000x reference)
#include <cuda_runtime.h>
#include <cstdint>

// Problem constants
#define B_ 512
#define F_ 1180
#define A_ 50
#define C_ 1024
#define W_ 19            // ceil(1180 / 64) u64 words per feature-bitmask
#define W_PAD 20         // padded stride for g_x
#define NCLAUSE (A_*C_)  // 51200

// Scratch (allocation-free rule: __device__ globals)
__device__ unsigned long long g_x[B_ * W_PAD];   // packed batch rows (full words)
__device__ unsigned long long g_x0[B_];          // dense word-0 copy (hot path)
__device__ float g_votes[B_ * A_];               // vote accumulator

// ---------------------------------------------------------------------------
// Bit permutation (MUST match between ta pack and x pack):
//   iter it in [0,9): lane loads float4 at it*128 + 4*lane.
//     word 2*it   : bit lane <- v.x,  bit 32+lane <- v.y
//     word 2*it+1 : bit lane <- v.z,  bit 32+lane <- v.w
//   word 18 (tail, 28 floats): bit lane <- row[1152+lane], lane<28; rest 0.
// Rows are 1180*4 = 4720 B = 295*16 B -> float4 loads stay 16B-aligned.
// ---------------------------------------------------------------------------

// Pack binary_features [B,F]: one block (64 threads = 2 warps) per row.
// Warp 0 packs iters 0..4; warp 1 packs iters 5..8 + tail. Also zeroes votes.
__global__ __launch_bounds__(64) void pack_x_kernel(const float* __restrict__ x) {
    const int tid    = threadIdx.x;
    const int lane   = tid & 31;
    const int w      = tid >> 5;
    const int row_id = blockIdx.x;

    // zero votes: 512 blocks x 64 threads = 32768 >= 25600 -> single pass
    {
        int i = row_id * 64 + tid;
        if (i < B_ * A_) g_votes[i] = 0.0f;
    }

    const float* row = x + (size_t)row_id * F_;
    unsigned long long* out = g_x + (size_t)row_id * W_PAD;

    const int it_lo = w ? 5 : 0;
    const int it_hi = w ? 9 : 5;

    float4 v[5];
#pragma unroll
    for (int k = 0; k < 5; ++k) {
        int it = it_lo + k;
        if (it < it_hi)
            v[k] = *reinterpret_cast<const float4*>(row + it * 128 + 4 * lane);
    }
    float ftail = -1.0f;
    if (w == 1 && lane < (F_ - 1152)) ftail = row[1152 + lane];

#pragma unroll
    for (int k = 0; k < 5; ++k) {
        int it = it_lo + k;
        if (it >= it_hi) break;
        unsigned a0 = __ballot_sync(0xffffffffu, v[k].x > 0.5f);
        unsigned a1 = __ballot_sync(0xffffffffu, v[k].y > 0.5f);
        unsigned b0 = __ballot_sync(0xffffffffu, v[k].z > 0.5f);
        unsigned b1 = __ballot_sync(0xffffffffu, v[k].w > 0.5f);
        if (lane == 0) {
            unsigned long long w0 = (unsigned long long)a0 | ((unsigned long long)a1 << 32);
            unsigned long long w1 = (unsigned long long)b0 | ((unsigned long long)b1 << 32);
            out[2 * it]     = w0;
            out[2 * it + 1] = w1;
            if (it == 0) g_x0[row_id] = w0;   // dense hot-path copy
        }
    }
    if (w == 1) {
        unsigned bt = __ballot_sync(0xffffffffu, ftail > 0.5f);
        if (lane == 0) out[18] = (unsigned long long)bt;
    }
}

// ---------------------------------------------------------------------------
// Fused pack+eval: one warp per clause. Packs pos & neg rows into smem word
// arrays, then evaluates all 512 batch rows against word 0. Word-0 survivors
// (astronomically rare for random data, but handled exactly) run the full
// 19-word check and atomically add their signed vote.
// ---------------------------------------------------------------------------
#define FW 8   // warps (=clauses) per block
__global__ __launch_bounds__(256) void fused_kernel(
    const float* __restrict__ ta,
    const float* __restrict__ sign)
{
    __shared__ unsigned long long s_pos[FW][W_ + 1];   // +1 pad
    __shared__ unsigned long long s_neg[FW][W_ + 1];
    __shared__ unsigned long long sx0[B_];             // 4 KB: word 0 of each row

    const int tid  = threadIdx.x;
    const int wib  = tid >> 5;
    const int lane = tid & 31;

    // Stage word-0 of all 512 packed batch rows (dense, coalesced).
    for (int i = tid; i < B_; i += 256)
        sx0[i] = g_x0[i];

    const int gw = blockIdx.x * FW + wib;    // global clause index
    const int a  = gw / C_;
    const int c  = gw - a * C_;

    const float* rowp = ta + ((size_t)gw * 2) * F_;       // pos row
    const float* rown = rowp + F_;                        // neg row

    // ---- pack both polarity rows, interleaved 2-deep for MLP ----
#pragma unroll
    for (int it = 0; it < 9; ++it) {
        float4 vp = *reinterpret_cast<const float4*>(rowp + it * 128 + 4 * lane);
        float4 vn = *reinterpret_cast<const float4*>(rown + it * 128 + 4 * lane);
        unsigned pa0 = __ballot_sync(0xffffffffu, vp.x > 16.0f);
        unsigned pa1 = __ballot_sync(0xffffffffu, vp.y > 16.0f);
        unsigned pb0 = __ballot_sync(0xffffffffu, vp.z > 16.0f);
        unsigned pb1 = __ballot_sync(0xffffffffu, vp.w > 16.0f);
        unsigned na0 = __ballot_sync(0xffffffffu, vn.x > 16.0f);
        unsigned na1 = __ballot_sync(0xffffffffu, vn.y > 16.0f);
        unsigned nb0 = __ballot_sync(0xffffffffu, vn.z > 16.0f);
        unsigned nb1 = __ballot_sync(0xffffffffu, vn.w > 16.0f);
        if (lane == 0) {
            s_pos[wib][2 * it]     = (unsigned long long)pa0 | ((unsigned long long)pa1 << 32);
            s_pos[wib][2 * it + 1] = (unsigned long long)pb0 | ((unsigned long long)pb1 << 32);
            s_neg[wib][2 * it]     = (unsigned long long)na0 | ((unsigned long long)na1 << 32);
            s_neg[wib][2 * it + 1] = (unsigned long long)nb0 | ((unsigned long long)nb1 << 32);
        }
    }
    {
        float fp = (lane < (F_ - 1152)) ? rowp[1152 + lane] : -1e9f;
        float fn = (lane < (F_ - 1152)) ? rown[1152 + lane] : -1e9f;
        unsigned btp = __ballot_sync(0xffffffffu, fp > 16.0f);
        unsigned btn = __ballot_sync(0xffffffffu, fn > 16.0f);
        if (lane == 0) {
            s_pos[wib][18] = (unsigned long long)btp;
            s_neg[wib][18] = (unsigned long long)btn;
        }
    }
    __syncwarp();
    const unsigned long long p0 = s_pos[wib][0];
    const unsigned long long n0 = s_neg[wib][0];

    __syncthreads();   // sx0 ready (also covers the smem word writes)

    // ---- evaluate 512 rows against word 0; lane handles rows lane+32k ----
    unsigned surv = 0;
#pragma unroll
    for (int k = 0; k < 16; ++k) {
        const unsigned long long x0 = sx0[lane + 32 * k];
        if (((p0 & ~x0) | (n0 & x0)) == 0ull) surv |= (1u << k);
    }

    // ---- rare exact path ----
    if (__ballot_sync(0xffffffffu, surv != 0u)) {
        const float sg = sign[a * C_ + c];
        while (surv) {
            const int k = __ffs(surv) - 1;
            surv &= surv - 1;
            const int r = lane + 32 * k;
            bool alive = true;
            for (int w = 1; w < W_; ++w) {
                const unsigned long long xw = g_x[(size_t)r * W_PAD + w];
                if ((s_pos[wib][w] & ~xw) | (s_neg[wib][w] & xw)) {
                    alive = false; break;
                }
            }
            if (alive) atomicAdd(&g_votes[r * A_ + a], sg);
        }
    }
}

// ---------------------------------------------------------------------------
// Epilogue: clip votes into the output.
// ---------------------------------------------------------------------------
__global__ void clip_kernel(const int* __restrict__ Tptr,
                            float* __restrict__ out)
{
    int i = blockIdx.x * blockDim.x + threadIdx.x;
    if (i >= B_ * A_) return;
    int ti = *Tptr;
    float Tf = (ti >= 0 && ti < (1 << 20)) ? (float)ti
                                           : *reinterpret_cast<const float*>(Tptr);
    float s = g_votes[i];
    out[i] = fminf(fmaxf(s, -Tf), Tf);
}

// ---------------------------------------------------------------------------
extern "C" void kernel_launch(void* const* d_in, const int* in_sizes, int n_in,
                              void* d_out, int out_size) {
    const float* x    = (const float*)d_in[0];   // [B, F]
    const float* ta   = (const float*)d_in[1];   // [A, C, 2, F]
    const float* sign = (const float*)d_in[2];   // [A, C]
    const int*   Tptr = (const int*)d_in[3];     // scalar
    float* out = (float*)d_out;                  // [B, A]

    pack_x_kernel<<<B_, 64>>>(x);                        // 512 blocks, 2 warps each
    fused_kernel<<<NCLAUSE / FW, 256>>>(ta, sign);       // 6400 blocks
    clip_kernel<<<(B_ * A_ + 255) / 256, 256>>>(Tptr, out);
}